// round 1
// baseline (speedup 1.0000x reference)
#include <cuda_runtime.h>

// RoiPoolingConv: img (1,192,192,48,64) f32, rois (1,R,6) i32 (x,y,z,w,h,d),
// pool_size=7. out (1,R,7,7,64) f32.
// Bilinear resize (align_corners=False, src = dst * in/out) of crop
// img[:, x:x+w, y:y+h, z, :].

#define XD 192
#define YD 192
#define ZD 48
#define CC 64
#define PP 7

__global__ __launch_bounds__(256) void roi_pool_kernel(
    const float* __restrict__ img,
    const int* __restrict__ rois,
    float* __restrict__ out,
    int total_vec)
{
    int tid = blockIdx.x * blockDim.x + threadIdx.x;
    if (tid >= total_vec) return;

    int c4   = tid & 15;        // which float4 of the 64 channels
    int cell = tid >> 4;        // (r, i, j)
    int j    = cell % PP;
    int t2   = cell / PP;
    int i    = t2 % PP;
    int r    = t2 / PP;

    // ROI fields (broadcast within each 16-thread group; L1-hit)
    const int* roi = rois + r * 6;
    int x = __ldg(roi + 0);
    int y = __ldg(roi + 1);
    int z = __ldg(roi + 2);
    int w = __ldg(roi + 3);
    int h = __ldg(roi + 4);

    // source coords in the crop: sx = i * (w / P)  (match reference fp order)
    float sx = (float)i * ((float)w / (float)PP);
    float sy = (float)j * ((float)h / (float)PP);
    int x0 = (int)floorf(sx);
    int y0 = (int)floorf(sy);
    float fx = sx - (float)x0;
    float fy = sy - (float)y0;

    // clamp within crop, offset into volume, clamp to bounds
    int x0a = min(max(x + min(max(x0,     0), w - 1), 0), XD - 1);
    int x1a = min(max(x + min(max(x0 + 1, 0), w - 1), 0), XD - 1);
    int y0a = min(max(y + min(max(y0,     0), h - 1), 0), YD - 1);
    int y1a = min(max(y + min(max(y0 + 1, 0), h - 1), 0), YD - 1);
    int zc  = min(max(z, 0), ZD - 1);

    int coff = c4 * 4;
    const float4* p00 = (const float4*)(img + ((((size_t)x0a * YD + y0a) * ZD + zc) * CC + coff));
    const float4* p10 = (const float4*)(img + ((((size_t)x1a * YD + y0a) * ZD + zc) * CC + coff));
    const float4* p01 = (const float4*)(img + ((((size_t)x0a * YD + y1a) * ZD + zc) * CC + coff));
    const float4* p11 = (const float4*)(img + ((((size_t)x1a * YD + y1a) * ZD + zc) * CC + coff));

    // issue all four loads before use -> MLP=4 hides DRAM latency
    float4 v00 = __ldg(p00);
    float4 v10 = __ldg(p10);
    float4 v01 = __ldg(p01);
    float4 v11 = __ldg(p11);

    float w00 = (1.0f - fx) * (1.0f - fy);
    float w10 = fx * (1.0f - fy);
    float w01 = (1.0f - fx) * fy;
    float w11 = fx * fy;

    float4 o;
    o.x = v00.x * w00 + v10.x * w10 + v01.x * w01 + v11.x * w11;
    o.y = v00.y * w00 + v10.y * w10 + v01.y * w01 + v11.y * w11;
    o.z = v00.z * w00 + v10.z * w10 + v01.z * w01 + v11.z * w11;
    o.w = v00.w * w00 + v10.w * w10 + v01.w * w01 + v11.w * w11;

    ((float4*)out)[((size_t)(r * PP * PP) + i * PP + j) * (CC / 4) + c4] = o;
}

extern "C" void kernel_launch(void* const* d_in, const int* in_sizes, int n_in,
                              void* d_out, int out_size)
{
    const float* img  = (const float*)d_in[0];
    const int*   rois = (const int*)d_in[1];
    float*       out  = (float*)d_out;

    // out_size = R * 7 * 7 * 64; one thread per float4
    int total_vec = out_size / 4;
    int threads = 256;
    int blocks = (total_vec + threads - 1) / threads;
    roi_pool_kernel<<<blocks, threads>>>(img, rois, out, total_vec);
}

// round 2
// speedup vs baseline: 1.0337x; 1.0337x over previous
#include <cuda_runtime.h>

// RoiPoolingConv: img (1,192,192,48,64) f32, rois (1,R,6) i32 (x,y,z,w,h,d),
// pool_size=7. out (1,R,7,7,64) f32.
// One thread per output scalar (r,i,j,c): 4 coalesced 4B gathers + lerp.

#define XD 192
#define YD 192
#define ZD 48
#define CC 64
#define PP 7

__global__ __launch_bounds__(256) void roi_pool_kernel(
    const float* __restrict__ img,
    const int* __restrict__ rois,
    float* __restrict__ out,
    int total)
{
    int tid = blockIdx.x * blockDim.x + threadIdx.x;
    if (tid >= total) return;

    int c    = tid & (CC - 1);   // channel
    int cell = tid >> 6;         // (r, i, j)
    int j    = cell % PP;
    int t2   = cell / PP;
    int i    = t2 % PP;
    int r    = t2 / PP;

    // ROI fields: stride 6 ints = 24B, 8B-aligned -> 3 x int2 loads (independent)
    const int2* roi2 = (const int2*)(rois + r * 6);
    int2 a = __ldg(roi2 + 0);   // x, y
    int2 b = __ldg(roi2 + 1);   // z, w
    int2 cd = __ldg(roi2 + 2);  // h, d
    int x = a.x, y = a.y, z = b.x, w = b.y, h = cd.x;

    // source coords in the crop: sx = i * (w / P) (reference fp order)
    float sx = (float)i * ((float)w / (float)PP);
    float sy = (float)j * ((float)h / (float)PP);
    int x0 = (int)floorf(sx);
    int y0 = (int)floorf(sy);
    float fx = sx - (float)x0;
    float fy = sy - (float)y0;

    // clamp within crop, offset into volume, clamp to bounds
    int x0a = min(max(x + min(max(x0,     0), w - 1), 0), XD - 1);
    int x1a = min(max(x + min(max(x0 + 1, 0), w - 1), 0), XD - 1);
    int y0a = min(max(y + min(max(y0,     0), h - 1), 0), YD - 1);
    int y1a = min(max(y + min(max(y0 + 1, 0), h - 1), 0), YD - 1);
    int zc  = min(max(z, 0), ZD - 1);

    // row base offsets (z,c fixed): idx = ((x*YD + y)*ZD + zc)*CC + c
    int base_z = zc * CC + c;
    const float* p00 = img + ((x0a * YD + y0a) * ZD) * CC + base_z;
    const float* p10 = img + ((x1a * YD + y0a) * ZD) * CC + base_z;
    const float* p01 = img + ((x0a * YD + y1a) * ZD) * CC + base_z;
    const float* p11 = img + ((x1a * YD + y1a) * ZD) * CC + base_z;

    // 4 independent loads in flight (MLP=4)
    float v00 = __ldg(p00);
    float v10 = __ldg(p10);
    float v01 = __ldg(p01);
    float v11 = __ldg(p11);

    float w00 = (1.0f - fx) * (1.0f - fy);
    float w10 = fx * (1.0f - fy);
    float w01 = (1.0f - fx) * fy;
    float w11 = fx * fy;

    out[tid] = v00 * w00 + v10 * w10 + v01 * w01 + v11 * w11;
}

extern "C" void kernel_launch(void* const* d_in, const int* in_sizes, int n_in,
                              void* d_out, int out_size)
{
    const float* img  = (const float*)d_in[0];
    const int*   rois = (const int*)d_in[1];
    float*       out  = (float*)d_out;

    int total = out_size;          // R * 7 * 7 * 64 scalars
    int threads = 256;
    int blocks = (total + threads - 1) / threads;
    roi_pool_kernel<<<blocks, threads>>>(img, rois, out, total);
}